// round 10
// baseline (speedup 1.0000x reference)
#include <cuda_runtime.h>
#include <cuda_fp16.h>
#include <math.h>
#include <stdint.h>

#define NB 8192
#define ND 2048
#define NH 512
#define NA 3
#define LNEPS 1e-5f
#define SQRT_D 45.25483399593904f

// ---------------- scratch (device globals; no allocation allowed) ----------
__device__ float g_h1[(size_t)NB * NH];
__device__ float g_h2[(size_t)NB * (NH / 2)];
__device__ float g_gf[(size_t)NB * ND];
__device__ float g_q[(size_t)NB * ND];       // ffn2 out
__device__ float g_attn[(size_t)NB * ND];
__device__ float g_res1[(size_t)NB * ND];
__device__ float g_bnsum[NA * ND];
__device__ float g_bnsq[NA * ND];
__device__ int   g_cnt[NA];
__device__ float g_u[ND];
__device__ float g_w[ND];
__device__ float g_c[1];
__device__ float g_zero[4096];               // zero bias (zero-initialized)
// half activation buffers
__device__ __half g_f1h[(size_t)NB * ND];
__device__ __half g_f2h[(size_t)NB * ND];
__device__ __half g_h1h[(size_t)NB * NH];
__device__ __half g_h2h[(size_t)NB * (NH / 2)];
__device__ __half g_gfh[(size_t)NB * ND];
__device__ __half g_mixh[(size_t)NB * ND];   // gfM half, overwritten in-place by mix
__device__ __half g_nrmh[(size_t)NB * ND];
__device__ __half g_midh[(size_t)NB * 2 * ND];   // FFN mid; also holds MT early
// half weights (transposed or raw)
__device__ __half g_wth[32112640];

#define OF_GW1T 0
#define OF_GW2T (OF_GW1T + 4096 * 512)
#define OF_GW3T (OF_GW2T + 512 * 256)
#define OF_QWH  (OF_GW3T + 256 * 2048)      /* qW raw half [2048,2048] */
#define OF_KWH  (OF_QWH + 2048 * 2048)      /* kW raw half [2048,2048] */
#define OF_VWT  (OF_KWH + 2048 * 2048)
#define OF_FW1T (OF_VWT + 2048 * 2048)
#define OF_FW2T (OF_FW1T + 2048 * 4096)

// ---------------- helpers ----------------
__device__ __forceinline__ float geluf(float x) {
    return 0.5f * x * (1.0f + erff(x * 0.70710678118654752f));
}
__device__ __forceinline__ uint32_t smem_u32(const void *p) {
    uint32_t a;
    asm("{ .reg .u64 t; cvta.to.shared.u64 t, %1; cvt.u32.u64 %0, t; }" : "=r"(a) : "l"(p));
    return a;
}
__device__ __forceinline__ uint32_t swz128(uint32_t off) {
    return off ^ ((off >> 3) & 0x70u);
}
__device__ __forceinline__ void cp16(uint32_t s, const void *g) {
    asm volatile("cp.async.cg.shared.global [%0], [%1], 16;" :: "r"(s), "l"(g));
}
__device__ __forceinline__ void cp_commit() { asm volatile("cp.async.commit_group;" ::: "memory"); }
template <int N> __device__ __forceinline__ void cp_wait() {
    asm volatile("cp.async.wait_group %0;" :: "n"(N) : "memory");
}
__device__ __forceinline__ void ldsm4(uint32_t *r, uint32_t addr) {
    asm volatile("ldmatrix.sync.aligned.m8n8.x4.shared.b16 {%0,%1,%2,%3}, [%4];"
                 : "=r"(r[0]), "=r"(r[1]), "=r"(r[2]), "=r"(r[3]) : "r"(addr));
}
__device__ __forceinline__ void mma16816(float *c, const uint32_t *a, const uint32_t *b) {
    asm volatile(
        "mma.sync.aligned.m16n8k16.row.col.f32.f16.f16.f32 "
        "{%0,%1,%2,%3}, {%4,%5,%6,%7}, {%8,%9}, {%0,%1,%2,%3};"
        : "+f"(c[0]), "+f"(c[1]), "+f"(c[2]), "+f"(c[3])
        : "r"(a[0]), "r"(a[1]), "r"(a[2]), "r"(a[3]), "r"(b[0]), "r"(b[1]));
}
__device__ __forceinline__ float dot4(float4 a, float4 b) {
    return a.x * b.x + a.y * b.y + a.z * b.z + a.w * b.w;
}

// two-value block reduction (sum); result broadcast to all threads
__device__ __forceinline__ void blockReduce2(float &a, float &b) {
    __shared__ float sa[32], sb[32];
#pragma unroll
    for (int o = 16; o; o >>= 1) {
        a += __shfl_xor_sync(0xFFFFFFFFu, a, o);
        b += __shfl_xor_sync(0xFFFFFFFFu, b, o);
    }
    const int lane = threadIdx.x & 31, w = threadIdx.x >> 5;
    const int nw = blockDim.x >> 5;
    if (nw > 1) {
        if (lane == 0) { sa[w] = a; sb[w] = b; }
        __syncthreads();
        a = (lane < nw) ? sa[lane] : 0.0f;
        b = (lane < nw) ? sb[lane] : 0.0f;
#pragma unroll
        for (int o = 16; o; o >>= 1) {
            a += __shfl_xor_sync(0xFFFFFFFFu, a, o);
            b += __shfl_xor_sync(0xFFFFFFFFu, b, o);
        }
        __syncthreads();
    }
}

// ---------------- weight transpose + f32->f16: in[K,N] -> out[N,K] --------
__global__ void transp(const float *__restrict__ in, __half *__restrict__ out,
                       int K, int N) {
    __shared__ float t[32][33];
    const int n0 = blockIdx.x * 32, k0 = blockIdx.y * 32;
#pragma unroll
    for (int i = threadIdx.y; i < 32; i += 8)
        t[i][threadIdx.x] = in[(size_t)(k0 + i) * N + n0 + threadIdx.x];
    __syncthreads();
#pragma unroll
    for (int i = threadIdx.y; i < 32; i += 8)
        out[(size_t)(n0 + i) * K + k0 + threadIdx.x] =
            __float2half_rn(t[threadIdx.x][i]);
}

// ---------------- f32 -> f16 convert ----------------
__global__ void cvt_half(const float4 *__restrict__ in, __half2 *__restrict__ out,
                         int n4) {
    int i = blockIdx.x * blockDim.x + threadIdx.x;
    if (i < n4) {
        float4 v = in[i];
        out[2 * i]     = __floats2half2_rn(v.x, v.y);
        out[2 * i + 1] = __floats2half2_rn(v.z, v.w);
    }
}

// ---------------- u = kW@qb, w = qW@kb, c = qb.kb ----------------
__global__ __launch_bounds__(256) void vec_uwc(
    const float *__restrict__ qW, const float *__restrict__ kW,
    const float *__restrict__ qb, const float *__restrict__ kb,
    float *__restrict__ u, float *__restrict__ w, float *__restrict__ c)
{
    const int r = blockIdx.x, t = threadIdx.x;
    float s = 0.0f, dummy = 0.0f;
    if (r < ND) {
        const float4 *row = (const float4 *)(kW + (size_t)r * ND);
        const float4 *v = (const float4 *)qb;
#pragma unroll
        for (int p = 0; p < 2; p++) s += dot4(row[t + p * 256], v[t + p * 256]);
        blockReduce2(s, dummy);
        if (t == 0) u[r] = s;
    } else if (r < 2 * ND) {
        const float4 *row = (const float4 *)(qW + (size_t)(r - ND) * ND);
        const float4 *v = (const float4 *)kb;
#pragma unroll
        for (int p = 0; p < 2; p++) s += dot4(row[t + p * 256], v[t + p * 256]);
        blockReduce2(s, dummy);
        if (t == 0) w[r - ND] = s;
    } else {
        const float4 *a = (const float4 *)qb;
        const float4 *v = (const float4 *)kb;
#pragma unroll
        for (int p = 0; p < 2; p++) s += dot4(a[t + p * 256], v[t + p * 256]);
        blockReduce2(s, dummy);
        if (t == 0) *c = s;
    }
}

// ---------------- fp16 GEMM: C = concat_K(A1,A2) @ WT^T + bias -------------
// CTA tile 128x128, K chunk 64, 3-stage cp.async pipeline, warp tile 32x64.
#define GT_M 128
#define GT_N 128
#define GKH 64
#define SMA_SZ (GT_M * GKH * 2)         // 16384
#define SMB_SZ (GT_N * GKH * 2)         // 16384
#define STAGE_SZ (SMA_SZ + SMB_SZ)      // 32768
#define NSTAGE 3
#define SM_TOTAL (1024 + NSTAGE * STAGE_SZ)  // 99328

template <int EPI>
__global__ __launch_bounds__(256, 1) void tgemm(
    const __half *__restrict__ A1, const __half *__restrict__ A2,
    const __half *__restrict__ WT, const float *__restrict__ bias,
    float *__restrict__ C, __half *__restrict__ Ch,
    int M, int N, int K1, int K2,
    const float *__restrict__ e1, const float *__restrict__ e2)
{
    extern __shared__ char smem[];
    const uint32_t sb = smem_u32(smem);
    const uint32_t tile0 = (sb + 1023) & ~1023u;
    const int tid = threadIdx.x;
    const int wid = tid >> 5, lane = tid & 31;
    const size_t rowBase = (size_t)blockIdx.y * GT_M;
    const size_t colBase = (size_t)blockIdx.x * GT_N;
    const int K = K1 + K2;
    const int niter = K / GKH;

    const int warpM = (wid >> 1) * 32, warpN = (wid & 1) * 64;

    // cp.async chunk mapping: A 4 chunks/thread, B 4 chunks/thread
    uint32_t aoff[4], boff[4];
    const __half *pA1[4], *pA2[4], *pB[4];
#pragma unroll
    for (int i = 0; i < 4; i++) {
        int c = tid + i * 256, r = c >> 3, k16 = c & 7;
        aoff[i] = swz128((uint32_t)(r * 128 + k16 * 16));
        pA1[i] = A1 + (rowBase + r) * (size_t)K1 + k16 * 8;
        pA2[i] = A2 + (rowBase + r) * (size_t)K2 + k16 * 8 - K1;
        boff[i] = SMA_SZ + aoff[i];
        pB[i] = WT + (colBase + r) * (size_t)K + k16 * 8;
    }

    // ldmatrix per-lane base addresses (swizzle pre-applied, column 0)
    uint32_t aBase[2];
    {
        uint32_t khiA = ((lane >> 4) & 1) * 16;
#pragma unroll
        for (int mt = 0; mt < 2; mt++) {
            int r = warpM + mt * 16 + (lane & 15);
            aBase[mt] = ((uint32_t)(r * 128 + ((r & 7) << 4))) ^ khiA;
        }
    }
    uint32_t bBase[4];
    {
        uint32_t khiB = ((lane >> 3) & 1) * 16;
#pragma unroll
        for (int p = 0; p < 4; p++) {
            int r = warpN + p * 16 + ((lane >> 4) & 1) * 8 + (lane & 7);
            bBase[p] = ((uint32_t)(r * 128 + ((r & 7) << 4))) ^ khiB;
        }
    }

    float acc[2][8][4];
#pragma unroll
    for (int mt = 0; mt < 2; mt++)
#pragma unroll
        for (int nt = 0; nt < 8; nt++)
#pragma unroll
            for (int j = 0; j < 4; j++) acc[mt][nt][j] = 0.0f;

    // stage loader
    auto load_stage = [&](int st, int kg) {
        const uint32_t tb = tile0 + st * STAGE_SZ;
        const bool s1 = kg < K1;
#pragma unroll
        for (int i = 0; i < 4; i++)
            cp16(tb + aoff[i], (s1 ? pA1[i] : pA2[i]) + kg);
#pragma unroll
        for (int i = 0; i < 4; i++) cp16(tb + boff[i], pB[i] + kg);
    };

    // prologue: stages 0,1
    load_stage(0, 0); cp_commit();
    if (niter > 1) load_stage(1, GKH);
    cp_commit();

    for (int it = 0; it < niter; ++it) {
        cp_wait<1>();
        __syncthreads();
        if (it + 2 < niter) load_stage((it + 2) % NSTAGE, (it + 2) * GKH);
        cp_commit();
        const uint32_t tA = tile0 + (it % NSTAGE) * STAGE_SZ;
        const uint32_t tB = tA + SMA_SZ;
#pragma unroll
        for (int k16 = 0; k16 < GKH / 16; ++k16) {
            const uint32_t kb2 = k16 * 32;
            uint32_t a[2][4];
            ldsm4(a[0], tA + (aBase[0] ^ kb2));
            ldsm4(a[1], tA + (aBase[1] ^ kb2));
            uint32_t bf[4][4];
#pragma unroll
            for (int p = 0; p < 4; p++) ldsm4(bf[p], tB + (bBase[p] ^ kb2));
#pragma unroll
            for (int mt = 0; mt < 2; mt++)
#pragma unroll
                for (int p = 0; p < 4; p++) {
                    mma16816(acc[mt][2 * p], a[mt], &bf[p][0]);
                    mma16816(acc[mt][2 * p + 1], a[mt], &bf[p][2]);
                }
        }
    }

    // epilogue
#pragma unroll
    for (int mt = 0; mt < 2; mt++) {
#pragma unroll
        for (int hf = 0; hf < 2; hf++) {
            const size_t m = rowBase + warpM + mt * 16 + (lane >> 2) + hf * 8;
            const size_t crow = m * (size_t)N;
#pragma unroll
            for (int nt = 0; nt < 8; nt++) {
                const size_t c0 = colBase + warpN + nt * 8 + (lane & 3) * 2;
                float v0 = acc[mt][nt][hf * 2 + 0] + bias[c0];
                float v1 = acc[mt][nt][hf * 2 + 1] + bias[c0 + 1];
                if (EPI == 1) { v0 = geluf(v0); v1 = geluf(v1); }
                if (EPI == 2) {
                    float s0 = 1.0f / (1.0f + expf(-v0));
                    float s1 = 1.0f / (1.0f + expf(-v1));
                    v0 = s0 * e1[crow + c0] + (1.0f - s0) * e2[crow + c0];
                    v1 = s1 * e1[crow + c0 + 1] + (1.0f - s1) * e2[crow + c0 + 1];
                }
                if (C) *(float2 *)(C + crow + c0) = make_float2(v0, v1);
                if (Ch) *(__half2 *)(Ch + crow + c0) = __floats2half2_rn(v0, v1);
            }
        }
    }
}

// ---------------- LN + exact GELU -> half out ----------------
__global__ void ln_gelu_h(const float *__restrict__ x, const float *__restrict__ g,
                          const float *__restrict__ b, __half *__restrict__ xh, int N)
{
    const size_t row = blockIdx.x;
    const float4 *xr = (const float4 *)(x + row * (size_t)N);
    const int t = threadIdx.x;
    float4 v = xr[t];
    float s = v.x + v.y + v.z + v.w;
    float sq = v.x * v.x + v.y * v.y + v.z * v.z + v.w * v.w;
    blockReduce2(s, sq);
    const float invN = 1.0f / (float)N;
    float mu = s * invN;
    float var = sq * invN - mu * mu;
    float rs = rsqrtf(var + LNEPS);
    float4 gv = ((const float4 *)g)[t];
    float4 bv = ((const float4 *)b)[t];
    v.x = geluf((v.x - mu) * rs * gv.x + bv.x);
    v.y = geluf((v.y - mu) * rs * gv.y + bv.y);
    v.z = geluf((v.z - mu) * rs * gv.z + bv.z);
    v.w = geluf((v.w - mu) * rs * gv.w + bv.w);
    __half2 *ho = (__half2 *)(xh + row * (size_t)N);
    ho[2 * t] = __floats2half2_rn(v.x, v.y);
    ho[2 * t + 1] = __floats2half2_rn(v.z, v.w);
}

// ---------------- scores + softmax + v-mix (gfM half in, mix overwrites) ---
__global__ __launch_bounds__(256) void scores_mix(
    const __half *__restrict__ gfMh, const float *__restrict__ f1,
    const float *__restrict__ f2, const float *__restrict__ gf,
    const float *__restrict__ uvec, const float *__restrict__ wvec,
    const float *__restrict__ cscal, __half *__restrict__ mixh)
{
    const size_t base4 = (size_t)blockIdx.x * (ND / 4);
    const int t = threadIdx.x;
    float4 f1v[2], f2v[2];
    float d1 = 0, d2 = 0, d3 = 0, d4 = 0, d5 = 0, dummy = 0;
    const __half2 *gm = (const __half2 *)gfMh + base4 * 2;
#pragma unroll
    for (int p = 0; p < 2; p++) {
        int idx = t + p * 256;
        float2 m0 = __half22float2(gm[2 * idx]);
        float2 m1 = __half22float2(gm[2 * idx + 1]);
        float4 m = make_float4(m0.x, m0.y, m1.x, m1.y);
        f1v[p] = ((const float4 *)f1)[base4 + idx];
        f2v[p] = ((const float4 *)f2)[base4 + idx];
        float4 g = ((const float4 *)gf)[base4 + idx];
        float4 uu = ((const float4 *)uvec)[idx];
        float4 ww = ((const float4 *)wvec)[idx];
        d1 += dot4(m, f1v[p]);
        d2 += dot4(m, f2v[p]);
        d3 += dot4(f1v[p], uu);
        d4 += dot4(f2v[p], uu);
        d5 += dot4(g, ww);
    }
    blockReduce2(d1, d2);
    blockReduce2(d3, d4);
    blockReduce2(d5, dummy);
    const float c = *cscal;
    float s1 = (d1 + d3 + d5 + c) * (1.0f / SQRT_D);
    float s2 = (d2 + d4 + d5 + c) * (1.0f / SQRT_D);
    float mx = fmaxf(s1, s2);
    float e1v = expf(s1 - mx), e2v = expf(s2 - mx);
    float w1 = e1v / (e1v + e2v), w2 = 1.0f - w1;
    __half2 *ho = (__half2 *)(mixh) + base4 * 2;
#pragma unroll
    for (int p = 0; p < 2; p++) {
        int idx = t + p * 256;
        float4 a = f1v[p], b = f2v[p];
        ho[2 * idx] = __floats2half2_rn(w1 * a.x + w2 * b.x, w1 * a.y + w2 * b.y);
        ho[2 * idx + 1] = __floats2half2_rn(w1 * a.z + w2 * b.z, w1 * a.w + w2 * b.w);
    }
}

// ---------------- gated = LN(gf+attn); res1 = LN(gated+f1) ----------------
__global__ __launch_bounds__(256) void post_ln(
    const float *__restrict__ gf, const float *__restrict__ attn,
    const float *__restrict__ f1,
    const float *__restrict__ alng, const float *__restrict__ alnb,
    const float *__restrict__ ln1g, const float *__restrict__ ln1b,
    float *__restrict__ out)
{
    const size_t base4 = (size_t)blockIdx.x * (ND / 4);
    const int t = threadIdx.x;
    float4 xv[2];
    float s = 0.0f, sq = 0.0f;
#pragma unroll
    for (int p = 0; p < 2; p++) {
        int idx = t + p * 256;
        float4 g = ((const float4 *)gf)[base4 + idx];
        float4 a = ((const float4 *)attn)[base4 + idx];
        float4 x;
        x.x = g.x + a.x; x.y = g.y + a.y; x.z = g.z + a.z; x.w = g.w + a.w;
        xv[p] = x;
        s += x.x + x.y + x.z + x.w;
        sq += x.x * x.x + x.y * x.y + x.z * x.z + x.w * x.w;
    }
    blockReduce2(s, sq);
    const float invD = 1.0f / (float)ND;
    float mu = s * invD;
    float var = sq * invD - mu * mu;
    float rs = rsqrtf(var + LNEPS);

    float4 yv[2];
    float s3 = 0.0f, sq3 = 0.0f;
#pragma unroll
    for (int p = 0; p < 2; p++) {
        int idx = t + p * 256;
        float4 gv = ((const float4 *)alng)[idx];
        float4 bv = ((const float4 *)alnb)[idx];
        float4 fv = ((const float4 *)f1)[base4 + idx];
        float4 x = xv[p], y;
        y.x = (x.x - mu) * rs * gv.x + bv.x + fv.x;
        y.y = (x.y - mu) * rs * gv.y + bv.y + fv.y;
        y.z = (x.z - mu) * rs * gv.z + bv.z + fv.z;
        y.w = (x.w - mu) * rs * gv.w + bv.w + fv.w;
        yv[p] = y;
        s3 += y.x + y.y + y.z + y.w;
        sq3 += y.x * y.x + y.y * y.y + y.z * y.z + y.w * y.w;
    }
    blockReduce2(s3, sq3);
    float mu2 = s3 * invD;
    float var2 = sq3 * invD - mu2 * mu2;
    float rs2 = rsqrtf(var2 + LNEPS);
#pragma unroll
    for (int p = 0; p < 2; p++) {
        int idx = t + p * 256;
        float4 gv = ((const float4 *)ln1g)[idx];
        float4 bv = ((const float4 *)ln1b)[idx];
        float4 y = yv[p], o;
        o.x = (y.x - mu2) * rs2 * gv.x + bv.x;
        o.y = (y.y - mu2) * rs2 * gv.y + bv.y;
        o.z = (y.z - mu2) * rs2 * gv.z + bv.z;
        o.w = (y.w - mu2) * rs2 * gv.w + bv.w;
        ((float4 *)out)[base4 + idx] = o;
    }
}

// ---------------- aspect BN ----------------
__global__ void bn_count(const int *__restrict__ ids) {
    __shared__ int c[NA];
    if (threadIdx.x < NA) c[threadIdx.x] = 0;
    __syncthreads();
    for (int i = threadIdx.x; i < NB; i += blockDim.x) atomicAdd(&c[ids[i]], 1);
    __syncthreads();
    if (threadIdx.x < NA) g_cnt[threadIdx.x] = c[threadIdx.x];
}

__global__ __launch_bounds__(256) void bn_stats(const float *__restrict__ x,
                                                const int *__restrict__ ids)
{
    __shared__ float ssum[NA][32], ssq[NA][32];
    const int lane = threadIdx.x & 31;
    const int stripe = threadIdx.x >> 5;
    const int c = blockIdx.x * 32 + lane;
    if (stripe == 0) {
#pragma unroll
        for (int a = 0; a < NA; a++) { ssum[a][lane] = 0.0f; ssq[a][lane] = 0.0f; }
    }
    __syncthreads();
    float s0 = 0, s1 = 0, s2 = 0, q0 = 0, q1 = 0, q2 = 0;
#pragma unroll 4
    for (int r = stripe; r < NB; r += 8) {
        int a = ids[r];
        float v = x[(size_t)r * ND + c];
        float vv = v * v;
        if (a == 0) { s0 += v; q0 += vv; }
        else if (a == 1) { s1 += v; q1 += vv; }
        else { s2 += v; q2 += vv; }
    }
    atomicAdd(&ssum[0][lane], s0); atomicAdd(&ssq[0][lane], q0);
    atomicAdd(&ssum[1][lane], s1); atomicAdd(&ssq[1][lane], q1);
    atomicAdd(&ssum[2][lane], s2); atomicAdd(&ssq[2][lane], q2);
    __syncthreads();
    if (stripe < NA) {
        g_bnsum[stripe * ND + c] = ssum[stripe][lane];
        g_bnsq[stripe * ND + c] = ssq[stripe][lane];
    }
}

// BN apply -> half only (for FFN input)
__global__ void bn_apply(const float *__restrict__ x, const int *__restrict__ ids,
                         const float *__restrict__ bng, const float *__restrict__ bnb,
                         __half *__restrict__ outh)
{
    const int i = blockIdx.x * blockDim.x + threadIdx.x;
    const int row = i >> 9;
    const int c4 = i & 511;
    const int a = ids[row];
    const int cnt = g_cnt[a];
    float4 v = ((const float4 *)x)[i];
    if (cnt > 1) {
        const float fc = (float)cnt;
        const int cb4 = (a * ND) / 4 + c4;
        float4 sm = ((const float4 *)g_bnsum)[cb4];
        float4 sc = ((const float4 *)g_bnsq)[cb4];
        float4 gv = ((const float4 *)bng)[cb4];
        float4 bv = ((const float4 *)bnb)[cb4];
        float m, vr;
        m = sm.x / fc; vr = sc.x / fc - m * m; v.x = (v.x - m) * rsqrtf(vr + LNEPS) * gv.x + bv.x;
        m = sm.y / fc; vr = sc.y / fc - m * m; v.y = (v.y - m) * rsqrtf(vr + LNEPS) * gv.y + bv.y;
        m = sm.z / fc; vr = sc.z / fc - m * m; v.z = (v.z - m) * rsqrtf(vr + LNEPS) * gv.z + bv.z;
        m = sm.w / fc; vr = sc.w / fc - m * m; v.w = (v.w - m) * rsqrtf(vr + LNEPS) * gv.w + bv.w;
    }
    __half2 *ho = (__half2 *)outh;
    ho[2 * i] = __floats2half2_rn(v.x, v.y);
    ho[2 * i + 1] = __floats2half2_rn(v.z, v.w);
}

// ---------------- final: out = LN(ffn2 + BN(res1)) ----------------
__global__ __launch_bounds__(256) void ln_residual_bn(
    const float *__restrict__ x, const float *__restrict__ res1,
    const int *__restrict__ ids,
    const float *__restrict__ bng, const float *__restrict__ bnb,
    const float *__restrict__ g, const float *__restrict__ b,
    float *__restrict__ out)
{
    const size_t row = blockIdx.x;
    const size_t base4 = row * (ND / 4);
    const int t = threadIdx.x;
    const int a = ids[row];
    const int cnt = g_cnt[a];
    const float fc = (float)cnt;
    const bool donorm = cnt > 1;
    float4 v[2];
    float s = 0.0f, sq = 0.0f;
#pragma unroll
    for (int p = 0; p < 2; p++) {
        int idx = t + p * 256;
        float4 r = ((const float4 *)res1)[base4 + idx];
        if (donorm) {
            const int cb4 = (a * ND) / 4 + idx;
            float4 sm = ((const float4 *)g_bnsum)[cb4];
            float4 sc = ((const float4 *)g_bnsq)[cb4];
            float4 gv = ((const float4 *)bng)[cb4];
            float4 bv = ((const float4 *)bnb)[cb4];
            float m, vr;
            m = sm.x / fc; vr = sc.x / fc - m * m; r.x = (r.x - m) * rsqrtf(vr + LNEPS) * gv.x + bv.x;
            m = sm.y / fc; vr = sc.y / fc - m * m; r.y = (r.y - m) * rsqrtf(vr + LNEPS) * gv.y + bv.y;
            m = sm.z / fc; vr = sc.z / fc - m * m; r.z = (r.z - m) * rsqrtf(vr + LNEPS) * gv.z + bv.z;
            m = sm.w / fc; vr = sc.w / fc - m * m; r.w = (r.w - m) * rsqrtf(vr + LNEPS) * gv.w + bv.w;
        }
        float4 xv = ((const float4 *)x)[base4 + idx];
        r.x += xv.x; r.y += xv.y; r.z += xv.z; r.w += xv.w;
        v[p] = r;
        s += r.x + r.y + r.z + r.w;
        sq += r.x * r.x + r.y * r.y + r.z * r.z + r.w * r.w;
    }
    blockReduce2(s, sq);
    const float invD = 1.0f / (float)ND;
    float mu = s * invD;
    float var = sq * invD - mu * mu;
    float rs = rsqrtf(var + LNEPS);
#pragma unroll
    for (int p = 0; p < 2; p++) {
        int idx = t + p * 256;
        float4 gv = ((const float4 *)g)[idx];
        float4 bv = ((const float4 *)b)[idx];
        float4 a2 = v[p], o;
        o.x = (a2.x - mu) * rs * gv.x + bv.x;
        o.y = (a2.y - mu) * rs * gv.y + bv.y;
        o.z = (a2.z - mu) * rs * gv.z + bv.z;
        o.w = (a2.w - mu) * rs * gv.w + bv.w;
        ((float4 *)out)[base4 + idx] = o;
    }
}

// ---------------- launch ----------------
extern "C" void kernel_launch(void *const *d_in, const int *in_sizes, int n_in,
                              void *d_out, int out_size)
{
    const float *f1 = (const float *)d_in[0];
    const float *f2 = (const float *)d_in[1];
    const int *ids = (const int *)d_in[2];
    const float *gW1 = (const float *)d_in[3], *gb1 = (const float *)d_in[4];
    const float *gl1g = (const float *)d_in[5], *gl1b = (const float *)d_in[6];
    const float *gW2 = (const float *)d_in[7], *gb2 = (const float *)d_in[8];
    const float *gl2g = (const float *)d_in[9], *gl2b = (const float *)d_in[10];
    const float *gW3 = (const float *)d_in[11], *gb3 = (const float *)d_in[12];
    const float *qW = (const float *)d_in[13], *qb = (const float *)d_in[14];
    const float *kW = (const float *)d_in[15], *kb = (const float *)d_in[16];
    const float *vW = (const float *)d_in[17], *vb = (const float *)d_in[18];
    const float *alng = (const float *)d_in[19], *alnb = (const float *)d_in[20];
    const float *bng = (const float *)d_in[21], *bnb = (const float *)d_in[22];
    const float *ln1g = (const float *)d_in[23], *ln1b = (const float *)d_in[24];
    const float *fW1 = (const float *)d_in[25], *fb1 = (const float *)d_in[26];
    const float *fW2 = (const float *)d_in[27], *fb2 = (const float *)d_in[28];
    const float *ln2g = (const float *)d_in[29], *ln2b = (const float *)d_in[30];
    float *out = (float *)d_out;

    float *h1, *h2, *gf, *q, *attn, *res1, *uv, *wv, *cv, *zb;
    __half *f1h, *f2h, *h1h, *h2h, *gfh, *mixh, *nrmh, *midh, *wth;
    cudaGetSymbolAddress((void **)&h1, g_h1);
    cudaGetSymbolAddress((void **)&h2, g_h2);
    cudaGetSymbolAddress((void **)&gf, g_gf);
    cudaGetSymbolAddress((void **)&q, g_q);
    cudaGetSymbolAddress((void **)&attn, g_attn);
    cudaGetSymbolAddress((void **)&res1, g_res1);
    cudaGetSymbolAddress((void **)&uv, g_u);
    cudaGetSymbolAddress((void **)&wv, g_w);
    cudaGetSymbolAddress((void **)&cv, g_c);
    cudaGetSymbolAddress((void **)&zb, g_zero);
    cudaGetSymbolAddress((void **)&f1h, g_f1h);
    cudaGetSymbolAddress((void **)&f2h, g_f2h);
    cudaGetSymbolAddress((void **)&h1h, g_h1h);
    cudaGetSymbolAddress((void **)&h2h, g_h2h);
    cudaGetSymbolAddress((void **)&gfh, g_gfh);
    cudaGetSymbolAddress((void **)&mixh, g_mixh);
    cudaGetSymbolAddress((void **)&nrmh, g_nrmh);
    cudaGetSymbolAddress((void **)&midh, g_midh);
    cudaGetSymbolAddress((void **)&wth, g_wth);

    cudaFuncSetAttribute(tgemm<0>, cudaFuncAttributeMaxDynamicSharedMemorySize, SM_TOTAL);
    cudaFuncSetAttribute(tgemm<1>, cudaFuncAttributeMaxDynamicSharedMemorySize, SM_TOTAL);
    cudaFuncSetAttribute(tgemm<2>, cudaFuncAttributeMaxDynamicSharedMemorySize, SM_TOTAL);

    // side stream for independent preprocessing (fork/join via events; capture-legal)
    cudaStream_t s2;
    cudaStreamCreateWithFlags(&s2, cudaStreamNonBlocking);
    cudaEvent_t evFork, evJoin;
    cudaEventCreateWithFlags(&evFork, cudaEventDisableTiming);
    cudaEventCreateWithFlags(&evJoin, cudaEventDisableTiming);

    dim3 tb(32, 8);
    cudaEventRecord(evFork, 0);
    cudaStreamWaitEvent(s2, evFork, 0);
    // ---- side stream: everything not needed until gfM / attn / BN / FFN ----
    cvt_half<<<(ND * ND / 4) / 256, 256, 0, s2>>>((const float4 *)qW, (__half2 *)(wth + OF_QWH), ND * ND / 4);
    cvt_half<<<(ND * ND / 4) / 256, 256, 0, s2>>>((const float4 *)kW, (__half2 *)(wth + OF_KWH), ND * ND / 4);
    transp<<<dim3(2048 / 32, 2048 / 32), tb, 0, s2>>>(vW, wth + OF_VWT, 2048, 2048);
    transp<<<dim3(4096 / 32, 2048 / 32), tb, 0, s2>>>(fW1, wth + OF_FW1T, 2048, 4096);
    transp<<<dim3(2048 / 32, 4096 / 32), tb, 0, s2>>>(fW2, wth + OF_FW2T, 4096, 2048);
    vec_uwc<<<2 * ND + 1, 256, 0, s2>>>(qW, kW, qb, kb, uv, wv, cv);
    bn_count<<<1, 256, 0, s2>>>(ids);
    // MT = kW @ qW^T (half out), stored in midh (free until FFN)
    tgemm<0><<<dim3(ND / GT_N, ND / GT_M), 256, SM_TOTAL, s2>>>(
        wth + OF_KWH, wth + OF_KWH, wth + OF_QWH, zb, nullptr, midh,
        ND, ND, ND, 0, nullptr, nullptr);
    cudaEventRecord(evJoin, s2);

    // ---- main stream: gate MLP chain ----
    transp<<<dim3(512 / 32, 4096 / 32), tb>>>(gW1, wth + OF_GW1T, 4096, 512);
    transp<<<dim3(256 / 32, 512 / 32), tb>>>(gW2, wth + OF_GW2T, 512, 256);
    transp<<<dim3(2048 / 32, 256 / 32), tb>>>(gW3, wth + OF_GW3T, 256, 2048);
    cvt_half<<<(NB * ND / 4) / 256, 256>>>((const float4 *)f1, (__half2 *)f1h, NB * ND / 4);
    cvt_half<<<(NB * ND / 4) / 256, 256>>>((const float4 *)f2, (__half2 *)f2h, NB * ND / 4);

    const dim3 gG1(NH / GT_N, NB / GT_M);        // 4 x 64
    const dim3 gG2((NH / 2) / GT_N, NB / GT_M);  // 2 x 64
    const dim3 gD(ND / GT_N, NB / GT_M);         // 16 x 64
    const dim3 g2D((2 * ND) / GT_N, NB / GT_M);  // 32 x 64

    tgemm<0><<<gG1, 256, SM_TOTAL>>>(f1h, f2h, wth + OF_GW1T, gb1, h1, nullptr,
                                     NB, NH, ND, ND, nullptr, nullptr);
    ln_gelu_h<<<NB, NH / 4>>>(h1, gl1g, gl1b, h1h, NH);
    tgemm<0><<<gG2, 256, SM_TOTAL>>>(h1h, h1h, wth + OF_GW2T, gb2, h2, nullptr,
                                     NB, NH / 2, NH, 0, nullptr, nullptr);
    ln_gelu_h<<<NB, (NH / 2) / 4>>>(h2, gl2g, gl2b, h2h, NH / 2);
    tgemm<2><<<gD, 256, SM_TOTAL>>>(h2h, h2h, wth + OF_GW3T, gb3, gf, gfh,
                                    NB, ND, NH / 2, 0, f1, f2);

    // join side stream before anything that needs its outputs
    cudaStreamWaitEvent(0, evJoin, 0);

    // gfM = gf @ M (half out, into mixh; consumed+overwritten in-place by scores_mix)
    tgemm<0><<<gD, 256, SM_TOTAL>>>(gfh, gfh, midh, zb, nullptr, mixh,
                                    NB, ND, ND, 0, nullptr, nullptr);
    scores_mix<<<NB, 256>>>(mixh, f1, f2, gf, uv, wv, cv, mixh);
    // attn = mix @ vW + vb
    tgemm<0><<<gD, 256, SM_TOTAL>>>(mixh, mixh, wth + OF_VWT, vb, attn, nullptr,
                                    NB, ND, ND, 0, nullptr, nullptr);
    post_ln<<<NB, 256>>>(gf, attn, f1, alng, alnb, ln1g, ln1b, res1);
    bn_stats<<<ND / 32, 256>>>(res1, ids);
    bn_apply<<<(NB * ND / 4) / 256, 256>>>(res1, ids, bng, bnb, nrmh);
    // FFN
    tgemm<1><<<g2D, 256, SM_TOTAL>>>(nrmh, nrmh, wth + OF_FW1T, fb1, nullptr, midh,
                                     NB, 2 * ND, ND, 0, nullptr, nullptr);
    tgemm<0><<<gD, 256, SM_TOTAL>>>(midh, midh, wth + OF_FW2T, fb2, q, nullptr,
                                    NB, ND, 2 * ND, 0, nullptr, nullptr);
    ln_residual_bn<<<NB, 256>>>(q, res1, ids, bng, bnb, ln2g, ln2b, out);
}

// round 13
// speedup vs baseline: 1.0760x; 1.0760x over previous
#include <cuda_runtime.h>
#include <cuda_fp16.h>
#include <math.h>
#include <stdint.h>

#define NB 8192
#define ND 2048
#define NH 512
#define NA 3
#define LNEPS 1e-5f
#define SQRT_D 45.25483399593904f

// ---------------- scratch (device globals; no allocation allowed) ----------
__device__ float g_h1[(size_t)NB * NH];
__device__ float g_h2[(size_t)NB * (NH / 2)];
__device__ float g_gf[(size_t)NB * ND];
__device__ float g_q[(size_t)NB * ND];       // ffn2 out
__device__ float g_res1[(size_t)NB * ND];
__device__ float g_bnsum[NA * ND];
__device__ float g_bnsq[NA * ND];
__device__ int   g_cnt[NA];
__device__ float g_u[ND];
__device__ float g_w[ND];
__device__ float g_c[1];
__device__ float g_zero[4096];               // zero bias (zero-initialized)
// half activation buffers
__device__ __half g_f1h[(size_t)NB * ND];
__device__ __half g_f2h[(size_t)NB * ND];
__device__ __half g_h1h[(size_t)NB * NH];
__device__ __half g_h2h[(size_t)NB * (NH / 2)];
__device__ __half g_gfh[(size_t)NB * ND];    // gf half; later reused as attn half
__device__ __half g_mixh[(size_t)NB * ND];   // gfM half, overwritten in-place by mix
__device__ __half g_nrmh[(size_t)NB * ND];
__device__ __half g_midh[(size_t)NB * 2 * ND];   // FFN mid; also holds MT early
// half weights (transposed or raw)
__device__ __half g_wth[32112640];

#define OF_GW1T 0
#define OF_GW2T (OF_GW1T + 4096 * 512)
#define OF_GW3T (OF_GW2T + 512 * 256)
#define OF_QWH  (OF_GW3T + 256 * 2048)      /* qW raw half [2048,2048] */
#define OF_KWH  (OF_QWH + 2048 * 2048)      /* kW raw half [2048,2048] */
#define OF_VWT  (OF_KWH + 2048 * 2048)
#define OF_FW1T (OF_VWT + 2048 * 2048)
#define OF_FW2T (OF_FW1T + 2048 * 4096)

// ---------------- helpers ----------------
__device__ __forceinline__ float geluf(float x) {
    return 0.5f * x * (1.0f + erff(x * 0.70710678118654752f));
}
__device__ __forceinline__ uint32_t smem_u32(const void *p) {
    uint32_t a;
    asm("{ .reg .u64 t; cvta.to.shared.u64 t, %1; cvt.u32.u64 %0, t; }" : "=r"(a) : "l"(p));
    return a;
}
__device__ __forceinline__ uint32_t swz128(uint32_t off) {
    return off ^ ((off >> 3) & 0x70u);
}
__device__ __forceinline__ void cp16(uint32_t s, const void *g) {
    asm volatile("cp.async.cg.shared.global [%0], [%1], 16;" :: "r"(s), "l"(g));
}
__device__ __forceinline__ void cp_commit() { asm volatile("cp.async.commit_group;" ::: "memory"); }
template <int N> __device__ __forceinline__ void cp_wait() {
    asm volatile("cp.async.wait_group %0;" :: "n"(N) : "memory");
}
__device__ __forceinline__ void ldsm4(uint32_t *r, uint32_t addr) {
    asm volatile("ldmatrix.sync.aligned.m8n8.x4.shared.b16 {%0,%1,%2,%3}, [%4];"
                 : "=r"(r[0]), "=r"(r[1]), "=r"(r[2]), "=r"(r[3]) : "r"(addr));
}
__device__ __forceinline__ void mma16816(float *c, const uint32_t *a, const uint32_t *b) {
    asm volatile(
        "mma.sync.aligned.m16n8k16.row.col.f32.f16.f16.f32 "
        "{%0,%1,%2,%3}, {%4,%5,%6,%7}, {%8,%9}, {%0,%1,%2,%3};"
        : "+f"(c[0]), "+f"(c[1]), "+f"(c[2]), "+f"(c[3])
        : "r"(a[0]), "r"(a[1]), "r"(a[2]), "r"(a[3]), "r"(b[0]), "r"(b[1]));
}
__device__ __forceinline__ float dot4(float4 a, float4 b) {
    return a.x * b.x + a.y * b.y + a.z * b.z + a.w * b.w;
}

// two-value block reduction (sum); result broadcast to all threads
__device__ __forceinline__ void blockReduce2(float &a, float &b) {
    __shared__ float sa[32], sb[32];
#pragma unroll
    for (int o = 16; o; o >>= 1) {
        a += __shfl_xor_sync(0xFFFFFFFFu, a, o);
        b += __shfl_xor_sync(0xFFFFFFFFu, b, o);
    }
    const int lane = threadIdx.x & 31, w = threadIdx.x >> 5;
    const int nw = blockDim.x >> 5;
    if (nw > 1) {
        if (lane == 0) { sa[w] = a; sb[w] = b; }
        __syncthreads();
        a = (lane < nw) ? sa[lane] : 0.0f;
        b = (lane < nw) ? sb[lane] : 0.0f;
#pragma unroll
        for (int o = 16; o; o >>= 1) {
            a += __shfl_xor_sync(0xFFFFFFFFu, a, o);
            b += __shfl_xor_sync(0xFFFFFFFFu, b, o);
        }
        __syncthreads();
    }
}

// ---------------- weight transpose + f32->f16: in[K,N] -> out[N,K] --------
__global__ void transp(const float *__restrict__ in, __half *__restrict__ out,
                       int K, int N) {
    __shared__ float t[32][33];
    const int n0 = blockIdx.x * 32, k0 = blockIdx.y * 32;
#pragma unroll
    for (int i = threadIdx.y; i < 32; i += 8)
        t[i][threadIdx.x] = in[(size_t)(k0 + i) * N + n0 + threadIdx.x];
    __syncthreads();
#pragma unroll
    for (int i = threadIdx.y; i < 32; i += 8)
        out[(size_t)(n0 + i) * K + k0 + threadIdx.x] =
            __float2half_rn(t[threadIdx.x][i]);
}

// ---------------- f32 -> f16 convert ----------------
__global__ void cvt_half(const float4 *__restrict__ in, __half2 *__restrict__ out,
                         int n4) {
    int i = blockIdx.x * blockDim.x + threadIdx.x;
    if (i < n4) {
        float4 v = in[i];
        out[2 * i]     = __floats2half2_rn(v.x, v.y);
        out[2 * i + 1] = __floats2half2_rn(v.z, v.w);
    }
}

// ---------------- u = kW@qb, w = qW@kb, c = qb.kb ----------------
__global__ __launch_bounds__(256) void vec_uwc(
    const float *__restrict__ qW, const float *__restrict__ kW,
    const float *__restrict__ qb, const float *__restrict__ kb,
    float *__restrict__ u, float *__restrict__ w, float *__restrict__ c)
{
    const int r = blockIdx.x, t = threadIdx.x;
    float s = 0.0f, dummy = 0.0f;
    if (r < ND) {
        const float4 *row = (const float4 *)(kW + (size_t)r * ND);
        const float4 *v = (const float4 *)qb;
#pragma unroll
        for (int p = 0; p < 2; p++) s += dot4(row[t + p * 256], v[t + p * 256]);
        blockReduce2(s, dummy);
        if (t == 0) u[r] = s;
    } else if (r < 2 * ND) {
        const float4 *row = (const float4 *)(qW + (size_t)(r - ND) * ND);
        const float4 *v = (const float4 *)kb;
#pragma unroll
        for (int p = 0; p < 2; p++) s += dot4(row[t + p * 256], v[t + p * 256]);
        blockReduce2(s, dummy);
        if (t == 0) w[r - ND] = s;
    } else {
        const float4 *a = (const float4 *)qb;
        const float4 *v = (const float4 *)kb;
#pragma unroll
        for (int p = 0; p < 2; p++) s += dot4(a[t + p * 256], v[t + p * 256]);
        blockReduce2(s, dummy);
        if (t == 0) *c = s;
    }
}

// ---------------- fp16 GEMM: C = concat_K(A1,A2) @ WT^T + bias -------------
// CTA tile 128x256, K chunk 64, 3-stage cp.async pipeline, warp tile 64x64.
#define GT_M 128
#define GT_N 256
#define GKH 64
#define SMA_SZ (GT_M * GKH * 2)         // 16384
#define SMB_SZ (GT_N * GKH * 2)         // 32768
#define STAGE_SZ (SMA_SZ + SMB_SZ)      // 49152
#define NSTAGE 3
#define SM_TOTAL (1024 + NSTAGE * STAGE_SZ)  // 148480

template <int EPI>
__global__ __launch_bounds__(256, 1) void tgemm(
    const __half *__restrict__ A1, const __half *__restrict__ A2,
    const __half *__restrict__ WT, const float *__restrict__ bias,
    float *__restrict__ C, __half *__restrict__ Ch,
    int M, int N, int K1, int K2,
    const float *__restrict__ e1, const float *__restrict__ e2)
{
    extern __shared__ char smem[];
    const uint32_t sb = smem_u32(smem);
    const uint32_t tile0 = (sb + 1023) & ~1023u;
    const int tid = threadIdx.x;
    const int wid = tid >> 5, lane = tid & 31;
    const size_t rowBase = (size_t)blockIdx.y * GT_M;
    const size_t colBase = (size_t)blockIdx.x * GT_N;
    const int K = K1 + K2;
    const int niter = K / GKH;

    const int warpM = (wid >> 2) * 64, warpN = (wid & 3) * 64;

    // cp.async chunk mapping: A 4 chunks/thread, B 8 chunks/thread
    uint32_t aoff[4], boff[8];
    const __half *pA1[4], *pA2[4], *pB[8];
#pragma unroll
    for (int i = 0; i < 4; i++) {
        int c = tid + i * 256, r = c >> 3, k16 = c & 7;
        aoff[i] = swz128((uint32_t)(r * 128 + k16 * 16));
        pA1[i] = A1 + (rowBase + r) * (size_t)K1 + k16 * 8;
        pA2[i] = A2 + (rowBase + r) * (size_t)K2 + k16 * 8 - K1;
    }
#pragma unroll
    for (int i = 0; i < 8; i++) {
        int c = tid + i * 256, r = c >> 3, k16 = c & 7;
        boff[i] = SMA_SZ + swz128((uint32_t)(r * 128 + k16 * 16));
        pB[i] = WT + (colBase + r) * (size_t)K + k16 * 8;
    }

    // ldmatrix per-lane base addresses (swizzle pre-applied, column 0)
    uint32_t aBase[4];
    {
        uint32_t khiA = ((lane >> 4) & 1) * 16;
#pragma unroll
        for (int mt = 0; mt < 4; mt++) {
            int r = warpM + mt * 16 + (lane & 15);
            aBase[mt] = ((uint32_t)(r * 128 + ((r & 7) << 4))) ^ khiA;
        }
    }
    uint32_t bBase[4];
    {
        uint32_t khiB = ((lane >> 3) & 1) * 16;
#pragma unroll
        for (int p = 0; p < 4; p++) {
            int r = warpN + p * 16 + ((lane >> 4) & 1) * 8 + (lane & 7);
            bBase[p] = ((uint32_t)(r * 128 + ((r & 7) << 4))) ^ khiB;
        }
    }

    float acc[4][8][4];
#pragma unroll
    for (int mt = 0; mt < 4; mt++)
#pragma unroll
        for (int nt = 0; nt < 8; nt++)
#pragma unroll
            for (int j = 0; j < 4; j++) acc[mt][nt][j] = 0.0f;

    // stage loader
    auto load_stage = [&](int st, int kg) {
        const uint32_t tb = tile0 + st * STAGE_SZ;
        const bool s1 = kg < K1;
#pragma unroll
        for (int i = 0; i < 4; i++)
            cp16(tb + aoff[i], (s1 ? pA1[i] : pA2[i]) + kg);
#pragma unroll
        for (int i = 0; i < 8; i++) cp16(tb + boff[i], pB[i] + kg);
    };

    // prologue: stages 0,1
    load_stage(0, 0); cp_commit();
    if (niter > 1) load_stage(1, GKH);
    cp_commit();

    for (int it = 0; it < niter; ++it) {
        // pending here: G(it), G(it+1). wait<1> drains exactly G(it);
        // after the commit below, G(it+1) and G(it+2) remain in flight.
        cp_wait<1>();
        __syncthreads();
        if (it + 2 < niter) load_stage((it + 2) % NSTAGE, (it + 2) * GKH);
        cp_commit();
        const uint32_t tA = tile0 + (it % NSTAGE) * STAGE_SZ;
        const uint32_t tB = tA + SMA_SZ;
#pragma unroll
        for (int k16 = 0; k16 < GKH / 16; ++k16) {
            const uint32_t kb2 = k16 * 32;
            uint32_t a[4][4];
#pragma unroll
            for (int mt = 0; mt < 4; mt++) ldsm4(a[mt], tA + (aBase[mt] ^ kb2));
            uint32_t bf[4][4];
#pragma unroll
            for (int p = 0; p < 4; p++) ldsm4(bf[p], tB + (bBase[p] ^ kb2));
#pragma unroll
            for (int mt = 0; mt < 4; mt++)
#pragma unroll
                for (int p = 0; p < 4; p++) {
                    mma16816(acc[mt][2 * p], a[mt], &bf[p][0]);
                    mma16816(acc[mt][2 * p + 1], a[mt], &bf[p][2]);
                }
        }
    }

    // epilogue
#pragma unroll
    for (int mt = 0; mt < 4; mt++) {
#pragma unroll
        for (int hf = 0; hf < 2; hf++) {
            const size_t m = rowBase + warpM + mt * 16 + (lane >> 2) + hf * 8;
            const size_t crow = m * (size_t)N;
#pragma unroll
            for (int nt = 0; nt < 8; nt++) {
                const size_t c0 = colBase + warpN + nt * 8 + (lane & 3) * 2;
                float v0 = acc[mt][nt][hf * 2 + 0] + bias[c0];
                float v1 = acc[mt][nt][hf * 2 + 1] + bias[c0 + 1];
                if (EPI == 1) { v0 = geluf(v0); v1 = geluf(v1); }
                if (EPI == 2) {
                    float s0 = 1.0f / (1.0f + expf(-v0));
                    float s1 = 1.0f / (1.0f + expf(-v1));
                    v0 = s0 * e1[crow + c0] + (1.0f - s0) * e2[crow + c0];
                    v1 = s1 * e1[crow + c0 + 1] + (1.0f - s1) * e2[crow + c0 + 1];
                }
                if (C) *(float2 *)(C + crow + c0) = make_float2(v0, v1);
                if (Ch) *(__half2 *)(Ch + crow + c0) = __floats2half2_rn(v0, v1);
            }
        }
    }
}

// ---------------- LN + exact GELU -> half out ----------------
__global__ void ln_gelu_h(const float *__restrict__ x, const float *__restrict__ g,
                          const float *__restrict__ b, __half *__restrict__ xh, int N)
{
    const size_t row = blockIdx.x;
    const float4 *xr = (const float4 *)(x + row * (size_t)N);
    const int t = threadIdx.x;
    float4 v = xr[t];
    float s = v.x + v.y + v.z + v.w;
    float sq = v.x * v.x + v.y * v.y + v.z * v.z + v.w * v.w;
    blockReduce2(s, sq);
    const float invN = 1.0f / (float)N;
    float mu = s * invN;
    float var = sq * invN - mu * mu;
    float rs = rsqrtf(var + LNEPS);
    float4 gv = ((const float4 *)g)[t];
    float4 bv = ((const float4 *)b)[t];
    v.x = geluf((v.x - mu) * rs * gv.x + bv.x);
    v.y = geluf((v.y - mu) * rs * gv.y + bv.y);
    v.z = geluf((v.z - mu) * rs * gv.z + bv.z);
    v.w = geluf((v.w - mu) * rs * gv.w + bv.w);
    __half2 *ho = (__half2 *)(xh + row * (size_t)N);
    ho[2 * t] = __floats2half2_rn(v.x, v.y);
    ho[2 * t + 1] = __floats2half2_rn(v.z, v.w);
}

// ---------------- scores + softmax + v-mix ----------------
// inputs: gfM half, f1/f2 half, gf fp32 (for gf.w dot); mix overwrites gfMh buf
__global__ __launch_bounds__(256) void scores_mix(
    const __half *__restrict__ gfMh, const __half *__restrict__ f1h,
    const __half *__restrict__ f2h, const float *__restrict__ gf,
    const float *__restrict__ uvec, const float *__restrict__ wvec,
    const float *__restrict__ cscal, __half *__restrict__ mixh)
{
    const size_t base4 = (size_t)blockIdx.x * (ND / 4);
    const int t = threadIdx.x;
    float4 f1v[2], f2v[2];
    float d1 = 0, d2 = 0, d3 = 0, d4 = 0, d5 = 0, dummy = 0;
    const __half2 *gm = (const __half2 *)gfMh + base4 * 2;
    const __half2 *p1 = (const __half2 *)f1h + base4 * 2;
    const __half2 *p2 = (const __half2 *)f2h + base4 * 2;
#pragma unroll
    for (int p = 0; p < 2; p++) {
        int idx = t + p * 256;
        float2 m0 = __half22float2(gm[2 * idx]);
        float2 m1 = __half22float2(gm[2 * idx + 1]);
        float4 m = make_float4(m0.x, m0.y, m1.x, m1.y);
        float2 a0 = __half22float2(p1[2 * idx]);
        float2 a1 = __half22float2(p1[2 * idx + 1]);
        f1v[p] = make_float4(a0.x, a0.y, a1.x, a1.y);
        float2 b0 = __half22float2(p2[2 * idx]);
        float2 b1 = __half22float2(p2[2 * idx + 1]);
        f2v[p] = make_float4(b0.x, b0.y, b1.x, b1.y);
        float4 g = ((const float4 *)gf)[base4 + idx];
        float4 uu = ((const float4 *)uvec)[idx];
        float4 ww = ((const float4 *)wvec)[idx];
        d1 += dot4(m, f1v[p]);
        d2 += dot4(m, f2v[p]);
        d3 += dot4(f1v[p], uu);
        d4 += dot4(f2v[p], uu);
        d5 += dot4(g, ww);
    }
    blockReduce2(d1, d2);
    blockReduce2(d3, d4);
    blockReduce2(d5, dummy);
    const float c = *cscal;
    float s1 = (d1 + d3 + d5 + c) * (1.0f / SQRT_D);
    float s2 = (d2 + d4 + d5 + c) * (1.0f / SQRT_D);
    float mx = fmaxf(s1, s2);
    float e1v = expf(s1 - mx), e2v = expf(s2 - mx);
    float w1 = e1v / (e1v + e2v), w2 = 1.0f - w1;
    __half2 *ho = (__half2 *)(mixh) + base4 * 2;
#pragma unroll
    for (int p = 0; p < 2; p++) {
        int idx = t + p * 256;
        float4 a = f1v[p], b = f2v[p];
        ho[2 * idx] = __floats2half2_rn(w1 * a.x + w2 * b.x, w1 * a.y + w2 * b.y);
        ho[2 * idx + 1] = __floats2half2_rn(w1 * a.z + w2 * b.z, w1 * a.w + w2 * b.w);
    }
}

// ---------------- gated = LN(gf+attn); res1 = LN(gated+f1) ----------------
// attn is half
__global__ __launch_bounds__(256) void post_ln(
    const float *__restrict__ gf, const __half *__restrict__ attnh,
    const float *__restrict__ f1,
    const float *__restrict__ alng, const float *__restrict__ alnb,
    const float *__restrict__ ln1g, const float *__restrict__ ln1b,
    float *__restrict__ out)
{
    const size_t base4 = (size_t)blockIdx.x * (ND / 4);
    const int t = threadIdx.x;
    const __half2 *ah = (const __half2 *)attnh + base4 * 2;
    float4 xv[2];
    float s = 0.0f, sq = 0.0f;
#pragma unroll
    for (int p = 0; p < 2; p++) {
        int idx = t + p * 256;
        float4 g = ((const float4 *)gf)[base4 + idx];
        float2 a0 = __half22float2(ah[2 * idx]);
        float2 a1 = __half22float2(ah[2 * idx + 1]);
        float4 x;
        x.x = g.x + a0.x; x.y = g.y + a0.y; x.z = g.z + a1.x; x.w = g.w + a1.y;
        xv[p] = x;
        s += x.x + x.y + x.z + x.w;
        sq += x.x * x.x + x.y * x.y + x.z * x.z + x.w * x.w;
    }
    blockReduce2(s, sq);
    const float invD = 1.0f / (float)ND;
    float mu = s * invD;
    float var = sq * invD - mu * mu;
    float rs = rsqrtf(var + LNEPS);

    float4 yv[2];
    float s3 = 0.0f, sq3 = 0.0f;
#pragma unroll
    for (int p = 0; p < 2; p++) {
        int idx = t + p * 256;
        float4 gv = ((const float4 *)alng)[idx];
        float4 bv = ((const float4 *)alnb)[idx];
        float4 fv = ((const float4 *)f1)[base4 + idx];
        float4 x = xv[p], y;
        y.x = (x.x - mu) * rs * gv.x + bv.x + fv.x;
        y.y = (x.y - mu) * rs * gv.y + bv.y + fv.y;
        y.z = (x.z - mu) * rs * gv.z + bv.z + fv.z;
        y.w = (x.w - mu) * rs * gv.w + bv.w + fv.w;
        yv[p] = y;
        s3 += y.x + y.y + y.z + y.w;
        sq3 += y.x * y.x + y.y * y.y + y.z * y.z + y.w * y.w;
    }
    blockReduce2(s3, sq3);
    float mu2 = s3 * invD;
    float var2 = sq3 * invD - mu2 * mu2;
    float rs2 = rsqrtf(var2 + LNEPS);
#pragma unroll
    for (int p = 0; p < 2; p++) {
        int idx = t + p * 256;
        float4 gv = ((const float4 *)ln1g)[idx];
        float4 bv = ((const float4 *)ln1b)[idx];
        float4 y = yv[p], o;
        o.x = (y.x - mu2) * rs2 * gv.x + bv.x;
        o.y = (y.y - mu2) * rs2 * gv.y + bv.y;
        o.z = (y.z - mu2) * rs2 * gv.z + bv.z;
        o.w = (y.w - mu2) * rs2 * gv.w + bv.w;
        ((float4 *)out)[base4 + idx] = o;
    }
}

// ---------------- aspect BN ----------------
__global__ void bn_count(const int *__restrict__ ids) {
    __shared__ int c[NA];
    if (threadIdx.x < NA) c[threadIdx.x] = 0;
    __syncthreads();
    for (int i = threadIdx.x; i < NB; i += blockDim.x) atomicAdd(&c[ids[i]], 1);
    __syncthreads();
    if (threadIdx.x < NA) g_cnt[threadIdx.x] = c[threadIdx.x];
}

__global__ __launch_bounds__(256) void bn_stats(const float *__restrict__ x,
                                                const int *__restrict__ ids)
{
    __shared__ float ssum[NA][32], ssq[NA][32];
    const int lane = threadIdx.x & 31;
    const int stripe = threadIdx.x >> 5;
    const int c = blockIdx.x * 32 + lane;
    if (stripe == 0) {
#pragma unroll
        for (int a = 0; a < NA; a++) { ssum[a][lane] = 0.0f; ssq[a][lane] = 0.0f; }
    }
    __syncthreads();
    float s0 = 0, s1 = 0, s2 = 0, q0 = 0, q1 = 0, q2 = 0;
#pragma unroll 4
    for (int r = stripe; r < NB; r += 8) {
        int a = ids[r];
        float v = x[(size_t)r * ND + c];
        float vv = v * v;
        if (a == 0) { s0 += v; q0 += vv; }
        else if (a == 1) { s1 += v; q1 += vv; }
        else { s2 += v; q2 += vv; }
    }
    atomicAdd(&ssum[0][lane], s0); atomicAdd(&ssq[0][lane], q0);
    atomicAdd(&ssum[1][lane], s1); atomicAdd(&ssq[1][lane], q1);
    atomicAdd(&ssum[2][lane], s2); atomicAdd(&ssq[2][lane], q2);
    __syncthreads();
    if (stripe < NA) {
        g_bnsum[stripe * ND + c] = ssum[stripe][lane];
        g_bnsq[stripe * ND + c] = ssq[stripe][lane];
    }
}

// BN apply -> half only (for FFN input)
__global__ void bn_apply(const float *__restrict__ x, const int *__restrict__ ids,
                         const float *__restrict__ bng, const float *__restrict__ bnb,
                         __half *__restrict__ outh)
{
    const int i = blockIdx.x * blockDim.x + threadIdx.x;
    const int row = i >> 9;
    const int c4 = i & 511;
    const int a = ids[row];
    const int cnt = g_cnt[a];
    float4 v = ((const float4 *)x)[i];
    if (cnt > 1) {
        const float fc = (float)cnt;
        const int cb4 = (a * ND) / 4 + c4;
        float4 sm = ((const float4 *)g_bnsum)[cb4];
        float4 sc = ((const float4 *)g_bnsq)[cb4];
        float4 gv = ((const float4 *)bng)[cb4];
        float4 bv = ((const float4 *)bnb)[cb4];
        float m, vr;
        m = sm.x / fc; vr = sc.x / fc - m * m; v.x = (v.x - m) * rsqrtf(vr + LNEPS) * gv.x + bv.x;
        m = sm.y / fc; vr = sc.y / fc - m * m; v.y = (v.y - m) * rsqrtf(vr + LNEPS) * gv.y + bv.y;
        m = sm.z / fc; vr = sc.z / fc - m * m; v.z = (v.z - m) * rsqrtf(vr + LNEPS) * gv.z + bv.z;
        m = sm.w / fc; vr = sc.w / fc - m * m; v.w = (v.w - m) * rsqrtf(vr + LNEPS) * gv.w + bv.w;
    }
    __half2 *ho = (__half2 *)outh;
    ho[2 * i] = __floats2half2_rn(v.x, v.y);
    ho[2 * i + 1] = __floats2half2_rn(v.z, v.w);
}

// ---------------- final: out = LN(ffn2 + BN(res1)) ----------------
__global__ __launch_bounds__(256) void ln_residual_bn(
    const float *__restrict__ x, const float *__restrict__ res1,
    const int *__restrict__ ids,
    const float *__restrict__ bng, const float *__restrict__ bnb,
    const float *__restrict__ g, const float *__restrict__ b,
    float *__restrict__ out)
{
    const size_t row = blockIdx.x;
    const size_t base4 = row * (ND / 4);
    const int t = threadIdx.x;
    const int a = ids[row];
    const int cnt = g_cnt[a];
    const float fc = (float)cnt;
    const bool donorm = cnt > 1;
    float4 v[2];
    float s = 0.0f, sq = 0.0f;
#pragma unroll
    for (int p = 0; p < 2; p++) {
        int idx = t + p * 256;
        float4 r = ((const float4 *)res1)[base4 + idx];
        if (donorm) {
            const int cb4 = (a * ND) / 4 + idx;
            float4 sm = ((const float4 *)g_bnsum)[cb4];
            float4 sc = ((const float4 *)g_bnsq)[cb4];
            float4 gv = ((const float4 *)bng)[cb4];
            float4 bv = ((const float4 *)bnb)[cb4];
            float m, vr;
            m = sm.x / fc; vr = sc.x / fc - m * m; r.x = (r.x - m) * rsqrtf(vr + LNEPS) * gv.x + bv.x;
            m = sm.y / fc; vr = sc.y / fc - m * m; r.y = (r.y - m) * rsqrtf(vr + LNEPS) * gv.y + bv.y;
            m = sm.z / fc; vr = sc.z / fc - m * m; r.z = (r.z - m) * rsqrtf(vr + LNEPS) * gv.z + bv.z;
            m = sm.w / fc; vr = sc.w / fc - m * m; r.w = (r.w - m) * rsqrtf(vr + LNEPS) * gv.w + bv.w;
        }
        float4 xv = ((const float4 *)x)[base4 + idx];
        r.x += xv.x; r.y += xv.y; r.z += xv.z; r.w += xv.w;
        v[p] = r;
        s += r.x + r.y + r.z + r.w;
        sq += r.x * r.x + r.y * r.y + r.z * r.z + r.w * r.w;
    }
    blockReduce2(s, sq);
    const float invD = 1.0f / (float)ND;
    float mu = s * invD;
    float var = sq * invD - mu * mu;
    float rs = rsqrtf(var + LNEPS);
#pragma unroll
    for (int p = 0; p < 2; p++) {
        int idx = t + p * 256;
        float4 gv = ((const float4 *)g)[idx];
        float4 bv = ((const float4 *)b)[idx];
        float4 a2 = v[p], o;
        o.x = (a2.x - mu) * rs * gv.x + bv.x;
        o.y = (a2.y - mu) * rs * gv.y + bv.y;
        o.z = (a2.z - mu) * rs * gv.z + bv.z;
        o.w = (a2.w - mu) * rs * gv.w + bv.w;
        ((float4 *)out)[base4 + idx] = o;
    }
}

// ---------------- launch ----------------
extern "C" void kernel_launch(void *const *d_in, const int *in_sizes, int n_in,
                              void *d_out, int out_size)
{
    const float *f1 = (const float *)d_in[0];
    const float *f2 = (const float *)d_in[1];
    const int *ids = (const int *)d_in[2];
    const float *gW1 = (const float *)d_in[3], *gb1 = (const float *)d_in[4];
    const float *gl1g = (const float *)d_in[5], *gl1b = (const float *)d_in[6];
    const float *gW2 = (const float *)d_in[7], *gb2 = (const float *)d_in[8];
    const float *gl2g = (const float *)d_in[9], *gl2b = (const float *)d_in[10];
    const float *gW3 = (const float *)d_in[11], *gb3 = (const float *)d_in[12];
    const float *qW = (const float *)d_in[13], *qb = (const float *)d_in[14];
    const float *kW = (const float *)d_in[15], *kb = (const float *)d_in[16];
    const float *vW = (const float *)d_in[17], *vb = (const float *)d_in[18];
    const float *alng = (const float *)d_in[19], *alnb = (const float *)d_in[20];
    const float *bng = (const float *)d_in[21], *bnb = (const float *)d_in[22];
    const float *ln1g = (const float *)d_in[23], *ln1b = (const float *)d_in[24];
    const float *fW1 = (const float *)d_in[25], *fb1 = (const float *)d_in[26];
    const float *fW2 = (const float *)d_in[27], *fb2 = (const float *)d_in[28];
    const float *ln2g = (const float *)d_in[29], *ln2b = (const float *)d_in[30];
    float *out = (float *)d_out;

    float *h1, *h2, *gf, *q, *res1, *uv, *wv, *cv, *zb;
    __half *f1h, *f2h, *h1h, *h2h, *gfh, *mixh, *nrmh, *midh, *wth;
    cudaGetSymbolAddress((void **)&h1, g_h1);
    cudaGetSymbolAddress((void **)&h2, g_h2);
    cudaGetSymbolAddress((void **)&gf, g_gf);
    cudaGetSymbolAddress((void **)&q, g_q);
    cudaGetSymbolAddress((void **)&res1, g_res1);
    cudaGetSymbolAddress((void **)&uv, g_u);
    cudaGetSymbolAddress((void **)&wv, g_w);
    cudaGetSymbolAddress((void **)&cv, g_c);
    cudaGetSymbolAddress((void **)&zb, g_zero);
    cudaGetSymbolAddress((void **)&f1h, g_f1h);
    cudaGetSymbolAddress((void **)&f2h, g_f2h);
    cudaGetSymbolAddress((void **)&h1h, g_h1h);
    cudaGetSymbolAddress((void **)&h2h, g_h2h);
    cudaGetSymbolAddress((void **)&gfh, g_gfh);
    cudaGetSymbolAddress((void **)&mixh, g_mixh);
    cudaGetSymbolAddress((void **)&nrmh, g_nrmh);
    cudaGetSymbolAddress((void **)&midh, g_midh);
    cudaGetSymbolAddress((void **)&wth, g_wth);

    cudaFuncSetAttribute(tgemm<0>, cudaFuncAttributeMaxDynamicSharedMemorySize, SM_TOTAL);
    cudaFuncSetAttribute(tgemm<1>, cudaFuncAttributeMaxDynamicSharedMemorySize, SM_TOTAL);
    cudaFuncSetAttribute(tgemm<2>, cudaFuncAttributeMaxDynamicSharedMemorySize, SM_TOTAL);

    // side stream for independent preprocessing (fork/join via events; capture-legal)
    cudaStream_t s2;
    cudaStreamCreateWithFlags(&s2, cudaStreamNonBlocking);
    cudaEvent_t evFork, evJoin;
    cudaEventCreateWithFlags(&evFork, cudaEventDisableTiming);
    cudaEventCreateWithFlags(&evJoin, cudaEventDisableTiming);

    dim3 tb(32, 8);
    cudaEventRecord(evFork, 0);
    cudaStreamWaitEvent(s2, evFork, 0);
    // ---- side stream: everything not needed until gfM / attn / BN / FFN ----
    cvt_half<<<(ND * ND / 4) / 256, 256, 0, s2>>>((const float4 *)qW, (__half2 *)(wth + OF_QWH), ND * ND / 4);
    cvt_half<<<(ND * ND / 4) / 256, 256, 0, s2>>>((const float4 *)kW, (__half2 *)(wth + OF_KWH), ND * ND / 4);
    transp<<<dim3(2048 / 32, 2048 / 32), tb, 0, s2>>>(vW, wth + OF_VWT, 2048, 2048);
    transp<<<dim3(4096 / 32, 2048 / 32), tb, 0, s2>>>(fW1, wth + OF_FW1T, 2048, 4096);
    transp<<<dim3(2048 / 32, 4096 / 32), tb, 0, s2>>>(fW2, wth + OF_FW2T, 4096, 2048);
    vec_uwc<<<2 * ND + 1, 256, 0, s2>>>(qW, kW, qb, kb, uv, wv, cv);
    bn_count<<<1, 256, 0, s2>>>(ids);
    // MT = kW @ qW^T (half out), stored in midh (free until FFN)
    tgemm<0><<<dim3(ND / GT_N, ND / GT_M), 256, SM_TOTAL, s2>>>(
        wth + OF_KWH, wth + OF_KWH, wth + OF_QWH, zb, nullptr, midh,
        ND, ND, ND, 0, nullptr, nullptr);
    cudaEventRecord(evJoin, s2);

    // ---- main stream: gate MLP chain ----
    transp<<<dim3(512 / 32, 4096 / 32), tb>>>(gW1, wth + OF_GW1T, 4096, 512);
    transp<<<dim3(256 / 32, 512 / 32), tb>>>(gW2, wth + OF_GW2T, 512, 256);
    transp<<<dim3(2048 / 32, 256 / 32), tb>>>(gW3, wth + OF_GW3T, 256, 2048);
    cvt_half<<<(NB * ND / 4) / 256, 256>>>((const float4 *)f1, (__half2 *)f1h, NB * ND / 4);
    cvt_half<<<(NB * ND / 4) / 256, 256>>>((const float4 *)f2, (__half2 *)f2h, NB * ND / 4);

    const dim3 gG1(NH / GT_N, NB / GT_M);        // 2 x 64
    const dim3 gG2((NH / 2) / GT_N, NB / GT_M);  // 1 x 64
    const dim3 gD(ND / GT_N, NB / GT_M);         // 8 x 64
    const dim3 g2D((2 * ND) / GT_N, NB / GT_M);  // 16 x 64

    tgemm<0><<<gG1, 256, SM_TOTAL>>>(f1h, f2h, wth + OF_GW1T, gb1, h1, nullptr,
                                     NB, NH, ND, ND, nullptr, nullptr);
    ln_gelu_h<<<NB, NH / 4>>>(h1, gl1g, gl1b, h1h, NH);
    tgemm<0><<<gG2, 256, SM_TOTAL>>>(h1h, h1h, wth + OF_GW2T, gb2, h2, nullptr,
                                     NB, NH / 2, NH, 0, nullptr, nullptr);
    ln_gelu_h<<<NB, (NH / 2) / 4>>>(h2, gl2g, gl2b, h2h, NH / 2);
    tgemm<2><<<gD, 256, SM_TOTAL>>>(h2h, h2h, wth + OF_GW3T, gb3, gf, gfh,
                                    NB, ND, NH / 2, 0, f1, f2);

    // join side stream before anything that needs its outputs
    cudaStreamWaitEvent(0, evJoin, 0);

    // gfM = gf @ M (half out, into mixh; consumed+overwritten in-place by scores_mix)
    tgemm<0><<<gD, 256, SM_TOTAL>>>(gfh, gfh, midh, zb, nullptr, mixh,
                                    NB, ND, ND, 0, nullptr, nullptr);
    scores_mix<<<NB, 256>>>(mixh, f1h, f2h, gf, uv, wv, cv, mixh);
    // attn = mix @ vW + vb  (half out, reusing gfh — gf half no longer needed)
    tgemm<0><<<gD, 256, SM_TOTAL>>>(mixh, mixh, wth + OF_VWT, vb, nullptr, gfh,
                                    NB, ND, ND, 0, nullptr, nullptr);
    post_ln<<<NB, 256>>>(gf, gfh, f1, alng, alnb, ln1g, ln1b, res1);
    bn_stats<<<ND / 32, 256>>>(res1, ids);
    bn_apply<<<(NB * ND / 4) / 256, 256>>>(res1, ids, bng, bnb, nrmh);
    // FFN
    tgemm<1><<<g2D, 256, SM_TOTAL>>>(nrmh, nrmh, wth + OF_FW1T, fb1, nullptr, midh,
                                     NB, 2 * ND, ND, 0, nullptr, nullptr);
    tgemm<0><<<gD, 256, SM_TOTAL>>>(midh, midh, wth + OF_FW2T, fb2, q, nullptr,
                                    NB, ND, 2 * ND, 0, nullptr, nullptr);
    ln_residual_bn<<<NB, 256>>>(q, res1, ids, bng, bnb, ln2g, ln2b, out);
}